// round 16
// baseline (speedup 1.0000x reference)
#include <cuda_runtime.h>
#include <math.h>

#define GA 8
#define NB 16384

__device__ float g_comb[NB * 160];
__device__ uint2 g_Pb[2560];      // attention W frags  [32 rows][80 n]
__device__ float g_AC[5120];      // A+C, [64 k][80 j]
__device__ float g_W2[80];
__device__ uint2 g_P1h[10240];    // mlp L1 W frags hi  [40 rows][256 n]
__device__ uint2 g_P1l[10240];    //                lo
__device__ uint2 g_P2h[8192];     // mlp L2 W frags hi  [64 rows][128 n]
__device__ uint2 g_P2l[8192];     //                lo

__device__ __forceinline__ unsigned pack_bf16x2(float lo, float hi) {
    unsigned r;   // low 16 bits <- lo, high 16 <- hi
    asm("cvt.rn.bf16x2.f32 %0, %1, %2;" : "=r"(r) : "f"(hi), "f"(lo));
    return r;
}
__device__ __forceinline__ float bflo(unsigned p) {
    return __uint_as_float(p << 16);
}
__device__ __forceinline__ float bfhi(unsigned p) {
    return __uint_as_float(p & 0xFFFF0000u);
}
__device__ __forceinline__ void mma_bf16(float* c,
                                         unsigned a0, unsigned a1, unsigned a2, unsigned a3,
                                         unsigned b0, unsigned b1) {
    asm volatile("mma.sync.aligned.m16n8k16.row.col.f32.bf16.bf16.f32 "
                 "{%0,%1,%2,%3}, {%4,%5,%6,%7}, {%8,%9}, {%0,%1,%2,%3};"
                 : "+f"(c[0]), "+f"(c[1]), "+f"(c[2]), "+f"(c[3])
                 : "r"(a0), "r"(a1), "r"(a2), "r"(a3), "r"(b0), "r"(b1));
}
__device__ __forceinline__ void cp_async16(float* smem_dst, const float* gsrc) {
    unsigned s = (unsigned)__cvta_generic_to_shared(smem_dst);
    asm volatile("cp.async.cg.shared.global [%0], [%1], 16;" :: "r"(s), "l"(gsrc));
}
__device__ __forceinline__ void cp_async_commit() {
    asm volatile("cp.async.commit_group;");
}
__device__ __forceinline__ void cp_async_wait_all() {
    asm volatile("cp.async.wait_group 0;" ::: "memory");
}
__device__ __forceinline__ void bar_grp(int id) {
    asm volatile("bar.sync %0, %1;" :: "r"(id), "r"(128) : "memory");
}

// ---------------------------------------------------------------------------
// Prep: attention W frags + AC + aw2, and MLP split-bf16 W frags.
// bf16 B-frag row r = ks*4+tig: pairs (k0,k0+1),(k0+8,k0+9), k0=ks*16+tig*2.
// ---------------------------------------------------------------------------
__global__ void din_prep(const float* __restrict__ aw1,
                         const float* __restrict__ aw2,
                         const float* __restrict__ mw1,
                         const float* __restrict__ mw2) {
    int idx = blockIdx.x * 256 + threadIdx.x;
    if (idx < 2560) {
        int r = idx / 80, n = idx - r * 80;
        int ks = r >> 2, tg = r & 3;
        int k0 = ks * 16 + tg * 2;
        float w[4];
        #pragma unroll
        for (int t = 0; t < 4; t++) {
            int kk = k0 + (t >> 1) * 8 + (t & 1);
            w[t] = (kk < 64)
                 ? aw1[(64 + kk) * 80 + n] - aw1[(128 + kk) * 80 + n]
                 : aw1[(192 + kk - 64) * 80 + n];
        }
        g_Pb[idx] = make_uint2(pack_bf16x2(w[0], w[1]), pack_bf16x2(w[2], w[3]));
    }
    if (idx < 5120) {
        int k = idx / 80, j = idx - k * 80;
        g_AC[idx] = aw1[k * 80 + j] + aw1[(128 + k) * 80 + j];
    }
    if (idx < 80) g_W2[idx] = aw2[idx];
    if (idx < 10240) {       // layer1 W frags, split hi/lo
        int r = idx >> 8, n = idx & 255;
        int k0 = (r >> 2) * 16 + (r & 3) * 2;
        float w0 = mw1[k0 * 256 + n],      w1 = mw1[(k0 + 1) * 256 + n];
        float w2 = mw1[(k0 + 8) * 256 + n], w3 = mw1[(k0 + 9) * 256 + n];
        unsigned h0 = pack_bf16x2(w0, w1), h1 = pack_bf16x2(w2, w3);
        unsigned l0 = pack_bf16x2(w0 - bflo(h0), w1 - bfhi(h0));
        unsigned l1 = pack_bf16x2(w2 - bflo(h1), w3 - bfhi(h1));
        g_P1h[idx] = make_uint2(h0, h1);
        g_P1l[idx] = make_uint2(l0, l1);
    }
    if (idx < 8192) {        // layer2 W frags, split hi/lo
        int r = idx >> 7, n = idx & 127;
        int k0 = (r >> 2) * 16 + (r & 3) * 2;
        float w0 = mw2[k0 * 128 + n],      w1 = mw2[(k0 + 1) * 128 + n];
        float w2 = mw2[(k0 + 8) * 128 + n], w3 = mw2[(k0 + 9) * 128 + n];
        unsigned h0 = pack_bf16x2(w0, w1), h1 = pack_bf16x2(w2, w3);
        unsigned l0 = pack_bf16x2(w0 - bflo(h0), w1 - bfhi(h0));
        unsigned l1 = pack_bf16x2(w2 - bflo(h1), w3 - bfhi(h1));
        g_P2h[idx] = make_uint2(h0, h1);
        g_P2l[idx] = make_uint2(l0, l1);
    }
}

// ---------------------------------------------------------------------------
// Attention: bf16 mma, B-frags read from L1/L2 (no smem staging).
// smem 16976 floats = 67904 B -> 3 CTAs/SM.
//  sH 4x3808 | sQ 512 | sR 640 | sW2 80 | sScore 128 | sWt 128 | sPool 256
// ---------------------------------------------------------------------------
__global__ __launch_bounds__(256, 3)
void din_attention_kernel(
    const int* __restrict__ customer_id,
    const int* __restrict__ cand_good,
    const int* __restrict__ cand_class,
    const int* __restrict__ hist_goods,
    const int* __restrict__ hist_classes,
    const float* __restrict__ user_table,
    const float* __restrict__ item_table,
    const float* __restrict__ cat_table,
    const float* __restrict__ ab1,
    const float* __restrict__ ab2)
{
    extern __shared__ float sm[];
    float* sH     = sm;                // 4 x 3808
    float* sQ     = sm + 15232;        // 512
    float* sR     = sm + 15744;        // 640 (stride 80)
    float* sW2    = sm + 16384;        // 80
    float* sScore = sm + 16464;        // 2 x 64
    float* sWt    = sm + 16592;        // 2 x 64
    float* sPool  = sm + 16720;        // 2 x 128

    const int tid  = threadIdx.x;
    const int warp = tid >> 5;
    const int lane = tid & 31;
    const int gid  = lane >> 2;
    const int tig  = lane & 3;
    const int grp  = warp >> 2;
    const int mt   = warp & 3;
    const int tg128 = tid & 127;
    const int b0   = blockIdx.x * GA;
    const float ab2v = __ldg(ab2);

    for (int idx = tid; idx < GA * 64; idx += 256) {
        int g = idx >> 6, d = idx & 63;
        int b = b0 + g;
        float v = (d < 32) ? item_table[cand_good[b] * 32 + d]
                           : cat_table[cand_class[b] * 32 + (d - 32)];
        sQ[idx] = v;
        g_comb[b * 160 + 32 + d] = v;
    }
    for (int idx = tid; idx < GA * 32; idx += 256) {
        int g = idx >> 5, d = idx & 31;
        int b = b0 + g;
        g_comb[b * 160 + d] = user_table[customer_id[b] * 32 + d];
    }
    // stage AC into sH region (stride 80) for the r-vector pass
    float* sAC = sH;
    #pragma unroll
    for (int i = 0; i < 5; i++) {
        int f4 = tid + 256 * i;
        *(float4*)&sAC[f4 * 4] = __ldg((const float4*)g_AC + f4);
    }
    if (tid < 80) sW2[tid] = g_W2[tid];
    __syncthreads();
    for (int idx = tid; idx < 640; idx += 256) {
        int g = idx / 80, j = idx - g * 80;
        float v = __ldg(&ab1[j]);
        #pragma unroll 8
        for (int k = 0; k < 64; k++)
            v += sQ[g * 64 + k] * sAC[k * 80 + j];
        sR[idx] = v;
    }
    __syncthreads();   // sR ready; sAC region free for H buffers

    const int barid = grp + 1;
    float* bufA = sH + (grp * 2) * 3808;
    float* bufB = sH + (grp * 2 + 1) * 3808;
    const int gfirst = grp * 4;

    {
        const int b = b0 + gfirst;
        for (int f4 = tg128; f4 < 800; f4 += 128) {
            int l = f4 >> 4, q4 = f4 & 15, d0 = q4 * 4;
            const float* src;
            if (d0 < 32) src = item_table + hist_goods[b * 50 + l] * 32 + d0;
            else         src = cat_table  + hist_classes[b * 50 + l] * 32 + (d0 - 32);
            cp_async16(&bufA[l * 68 + d0], src);
        }
        cp_async_commit();
        cp_async_wait_all();
        bar_grp(barid);
    }

    const int r_lo = mt * 16 + gid;
    const int r_hi = r_lo + 8;

    for (int i = 0; i < 4; i++) {
        const int gg = gfirst + i;
        const int b  = b0 + gg;
        float* Hc = (i & 1) ? bufB : bufA;
        float* Ha = (i & 1) ? bufA : bufB;

        if (i < 3) {
            const int bn = b + 1;
            for (int f4 = tg128; f4 < 800; f4 += 128) {
                int l = f4 >> 4, q4 = f4 & 15, d0 = q4 * 4;
                const float* src;
                if (d0 < 32) src = item_table + hist_goods[bn * 50 + l] * 32 + d0;
                else         src = cat_table  + hist_classes[bn * 50 + l] * 32 + (d0 - 32);
                cp_async16(&Ha[l * 68 + d0], src);
            }
            cp_async_commit();
        }
        int mk0 = 1, mk1 = 1;
        if (tig == 0) {
            if (r_lo < 50) mk0 = hist_goods[b * 50 + r_lo];
            if (r_hi < 50) mk1 = hist_goods[b * 50 + r_hi];
        }

        // ---- bf16 MMA: rows [mt*16, +16), all n=80, K=128; B from L1 ----
        float acc[10][4];
        #pragma unroll
        for (int nt = 0; nt < 10; nt++)
            acc[nt][0] = acc[nt][1] = acc[nt][2] = acc[nt][3] = 0.f;

        #pragma unroll
        for (int ks = 0; ks < 8; ks++) {
            unsigned a0, a1, a2, a3;
            if (ks < 4) {
                const int c = ks * 16 + tig * 2;
                float2 x0 = *(const float2*)&Hc[r_lo * 68 + c];
                float2 x1 = *(const float2*)&Hc[r_hi * 68 + c];
                float2 x2 = *(const float2*)&Hc[r_lo * 68 + c + 8];
                float2 x3 = *(const float2*)&Hc[r_hi * 68 + c + 8];
                a0 = pack_bf16x2(x0.x, x0.y);
                a1 = pack_bf16x2(x1.x, x1.y);
                a2 = pack_bf16x2(x2.x, x2.y);
                a3 = pack_bf16x2(x3.x, x3.y);
            } else {
                const int c = (ks - 4) * 16 + tig * 2;
                float2 x0 = *(const float2*)&Hc[r_lo * 68 + c];
                float2 x1 = *(const float2*)&Hc[r_hi * 68 + c];
                float2 x2 = *(const float2*)&Hc[r_lo * 68 + c + 8];
                float2 x3 = *(const float2*)&Hc[r_hi * 68 + c + 8];
                float2 ql = *(const float2*)&sQ[gg * 64 + c];
                float2 qh = *(const float2*)&sQ[gg * 64 + c + 8];
                a0 = pack_bf16x2(x0.x * ql.x, x0.y * ql.y);
                a1 = pack_bf16x2(x1.x * ql.x, x1.y * ql.y);
                a2 = pack_bf16x2(x2.x * qh.x, x2.y * qh.y);
                a3 = pack_bf16x2(x3.x * qh.x, x3.y * qh.y);
            }
            const uint2* P = g_Pb + (ks * 4 + tig) * 80;
            #pragma unroll
            for (int nt = 0; nt < 10; nt++) {
                uint2 bb = __ldg(&P[nt * 8 + gid]);
                mma_bf16(acc[nt], a0, a1, a2, a3, bb.x, bb.y);
            }
        }

        float slo = 0.f, shi = 0.f;
        #pragma unroll
        for (int nt = 0; nt < 10; nt++) {
            const int j0 = nt * 8 + tig * 2;
            float r0v = sR[gg * 80 + j0], r1v = sR[gg * 80 + j0 + 1];
            float w0 = sW2[j0], w1 = sW2[j0 + 1];
            slo += fmaxf(acc[nt][0] + r0v, 0.f) * w0
                 + fmaxf(acc[nt][1] + r1v, 0.f) * w1;
            shi += fmaxf(acc[nt][2] + r0v, 0.f) * w0
                 + fmaxf(acc[nt][3] + r1v, 0.f) * w1;
        }
        slo += __shfl_down_sync(0xFFFFFFFFu, slo, 2, 4);
        slo += __shfl_down_sync(0xFFFFFFFFu, slo, 1, 4);
        shi += __shfl_down_sync(0xFFFFFFFFu, shi, 2, 4);
        shi += __shfl_down_sync(0xFFFFFFFFu, shi, 1, 4);
        if (tig == 0) {
            if (r_lo < 50)
                sScore[grp * 64 + r_lo] = (mk0 == 0) ? -1e9f : slo + ab2v;
            if (r_hi < 50)
                sScore[grp * 64 + r_hi] = (mk1 == 0) ? -1e9f : shi + ab2v;
        }
        bar_grp(barid);

        if (mt == 0) {
            float s0 = (lane < 50) ? sScore[grp * 64 + lane] : -INFINITY;
            float s1 = (lane + 32 < 50) ? sScore[grp * 64 + lane + 32] : -INFINITY;
            float mx = fmaxf(s0, s1);
            #pragma unroll
            for (int o = 16; o > 0; o >>= 1)
                mx = fmaxf(mx, __shfl_xor_sync(0xFFFFFFFFu, mx, o));
            float e0 = (lane < 50) ? expf(s0 - mx) : 0.f;
            float e1 = (lane + 32 < 50) ? expf(s1 - mx) : 0.f;
            float sum = e0 + e1;
            #pragma unroll
            for (int o = 16; o > 0; o >>= 1)
                sum += __shfl_xor_sync(0xFFFFFFFFu, sum, o);
            float inv = 1.f / sum;
            if (lane < 50) sWt[grp * 64 + lane] = e0 * inv;
            if (lane + 32 < 50) sWt[grp * 64 + lane + 32] = e1 * inv;
        }
        bar_grp(barid);

        {
            int d = tg128 & 63, lh = tg128 >> 6;
            int l0 = lh * 25;
            float p = 0.f;
            #pragma unroll 5
            for (int l = l0; l < l0 + 25; l++)
                p += sWt[grp * 64 + l] * Hc[l * 68 + d];
            sPool[grp * 128 + tg128] = p;
        }
        if (i < 3) cp_async_wait_all();
        bar_grp(barid);
        if (tg128 < 64)
            g_comb[b * 160 + 96 + tg128] =
                sPool[grp * 128 + tg128] + sPool[grp * 128 + 64 + tg128];
    }
}

// ---------------------------------------------------------------------------
// MLP: split-bf16 tensor-core 160->256->128->1 (unchanged from R15-pass).
// ---------------------------------------------------------------------------
__global__ __launch_bounds__(256, 3)
void din_mlp_kernel(const float* __restrict__ mb1,
                    const float* __restrict__ mb2,
                    const float* __restrict__ mw3,
                    const float* __restrict__ mb3,
                    float* __restrict__ out)
{
    extern __shared__ float smf[];
    unsigned* sXh  = (unsigned*)smf;          // 32 x 84
    unsigned* sXl  = sXh + 2688;              // 32 x 84
    unsigned* sZ1h = sXl + 2688;              // 32 x 132
    unsigned* sZ1l = sZ1h + 4224;             // 32 x 132
    float*    sZ2  = (float*)(sZ1l + 4224);   // 32 x 132
    float*    sW3  = sZ2 + 4224;              // 128

    const int tid  = threadIdx.x;
    const int warp = tid >> 5;
    const int lane = tid & 31;
    const int gid  = lane >> 2;
    const int tig  = lane & 3;
    const int b0   = blockIdx.x * 32;

    #pragma unroll
    for (int i = 0; i < 10; i++) {
        int v = tid + 256 * i;
        int row = v / 80, w = v - row * 80;
        float2 x = *(const float2*)&g_comb[(b0 + row) * 160 + w * 2];
        unsigned h = pack_bf16x2(x.x, x.y);
        unsigned l = pack_bf16x2(x.x - bflo(h), x.y - bfhi(h));
        sXh[row * 84 + w] = h;
        sXl[row * 84 + w] = l;
    }
    if (tid < 128) sW3[tid] = mw3[tid];
    __syncthreads();

    const int nb1 = warp * 32;
    float acc1[4][2][4];
    #pragma unroll
    for (int nt = 0; nt < 4; nt++)
        #pragma unroll
        for (int m = 0; m < 2; m++)
            acc1[nt][m][0] = acc1[nt][m][1] = acc1[nt][m][2] = acc1[nt][m][3] = 0.f;

    #pragma unroll
    for (int ks = 0; ks < 10; ks++) {
        unsigned ah[2][4], al[2][4];
        #pragma unroll
        for (int m = 0; m < 2; m++) {
            int rl = (m * 16 + gid) * 84, rh = rl + 8 * 84;
            int wi = ks * 8 + tig;
            ah[m][0] = sXh[rl + wi];     al[m][0] = sXl[rl + wi];
            ah[m][1] = sXh[rh + wi];     al[m][1] = sXl[rh + wi];
            ah[m][2] = sXh[rl + wi + 4]; al[m][2] = sXl[rl + wi + 4];
            ah[m][3] = sXh[rh + wi + 4]; al[m][3] = sXl[rh + wi + 4];
        }
        #pragma unroll
        for (int nt = 0; nt < 4; nt++) {
            int bi = (ks * 4 + tig) * 256 + nb1 + nt * 8 + gid;
            uint2 bh = __ldg(&g_P1h[bi]);
            uint2 bl = __ldg(&g_P1l[bi]);
            #pragma unroll
            for (int m = 0; m < 2; m++) {
                mma_bf16(acc1[nt][m], ah[m][0], ah[m][1], ah[m][2], ah[m][3], bh.x, bh.y);
                mma_bf16(acc1[nt][m], al[m][0], al[m][1], al[m][2], al[m][3], bh.x, bh.y);
                mma_bf16(acc1[nt][m], ah[m][0], ah[m][1], ah[m][2], ah[m][3], bl.x, bl.y);
            }
        }
    }
    #pragma unroll
    for (int nt = 0; nt < 4; nt++) {
        int j0 = nb1 + nt * 8 + tig * 2;
        float b0v = __ldg(&mb1[j0]), b1v = __ldg(&mb1[j0 + 1]);
        int wx = (j0 >> 1);
        #pragma unroll
        for (int m = 0; m < 2; m++) {
            int rl = m * 16 + gid;
            float v0 = fmaxf(acc1[nt][m][0] + b0v, 0.f);
            float v1 = fmaxf(acc1[nt][m][1] + b1v, 0.f);
            float v2 = fmaxf(acc1[nt][m][2] + b0v, 0.f);
            float v3 = fmaxf(acc1[nt][m][3] + b1v, 0.f);
            unsigned h0 = pack_bf16x2(v0, v1);
            unsigned h1 = pack_bf16x2(v2, v3);
            sZ1h[rl * 132 + wx] = h0;
            sZ1l[rl * 132 + wx] = pack_bf16x2(v0 - bflo(h0), v1 - bfhi(h0));
            sZ1h[(rl + 8) * 132 + wx] = h1;
            sZ1l[(rl + 8) * 132 + wx] = pack_bf16x2(v2 - bflo(h1), v3 - bfhi(h1));
        }
    }
    __syncthreads();

    const int nb2 = warp * 16;
    float acc2[2][2][4];
    #pragma unroll
    for (int nt = 0; nt < 2; nt++)
        #pragma unroll
        for (int m = 0; m < 2; m++)
            acc2[nt][m][0] = acc2[nt][m][1] = acc2[nt][m][2] = acc2[nt][m][3] = 0.f;

    #pragma unroll
    for (int ks = 0; ks < 16; ks++) {
        unsigned ah[2][4], al[2][4];
        #pragma unroll
        for (int m = 0; m < 2; m++) {
            int rl = (m * 16 + gid) * 132, rh = rl + 8 * 132;
            int wi = ks * 8 + tig;
            ah[m][0] = sZ1h[rl + wi];     al[m][0] = sZ1l[rl + wi];
            ah[m][1] = sZ1h[rh + wi];     al[m][1] = sZ1l[rh + wi];
            ah[m][2] = sZ1h[rl + wi + 4]; al[m][2] = sZ1l[rl + wi + 4];
            ah[m][3] = sZ1h[rh + wi + 4]; al[m][3] = sZ1l[rh + wi + 4];
        }
        #pragma unroll
        for (int nt = 0; nt < 2; nt++) {
            int bi = (ks * 4 + tig) * 128 + nb2 + nt * 8 + gid;
            uint2 bh = __ldg(&g_P2h[bi]);
            uint2 bl = __ldg(&g_P2l[bi]);
            #pragma unroll
            for (int m = 0; m < 2; m++) {
                mma_bf16(acc2[nt][m], ah[m][0], ah[m][1], ah[m][2], ah[m][3], bh.x, bh.y);
                mma_bf16(acc2[nt][m], al[m][0], al[m][1], al[m][2], al[m][3], bh.x, bh.y);
                mma_bf16(acc2[nt][m], ah[m][0], ah[m][1], ah[m][2], ah[m][3], bl.x, bl.y);
            }
        }
    }
    #pragma unroll
    for (int nt = 0; nt < 2; nt++) {
        int j0 = nb2 + nt * 8 + tig * 2;
        float b0v = __ldg(&mb2[j0]), b1v = __ldg(&mb2[j0 + 1]);
        #pragma unroll
        for (int m = 0; m < 2; m++) {
            int rl = m * 16 + gid;
            float2 zlo = make_float2(fmaxf(acc2[nt][m][0] + b0v, 0.f),
                                     fmaxf(acc2[nt][m][1] + b1v, 0.f));
            float2 zhi = make_float2(fmaxf(acc2[nt][m][2] + b0v, 0.f),
                                     fmaxf(acc2[nt][m][3] + b1v, 0.f));
            *(float2*)&sZ2[rl * 132 + j0] = zlo;
            *(float2*)&sZ2[(rl + 8) * 132 + j0] = zhi;
        }
    }
    __syncthreads();

    {
        int row = tid >> 3, seg = tid & 7;
        float p = 0.f;
        #pragma unroll
        for (int k = seg * 16; k < seg * 16 + 16; k++)
            p += sZ2[row * 132 + k] * sW3[k];
        #pragma unroll
        for (int o = 4; o > 0; o >>= 1)
            p += __shfl_down_sync(0xFFFFFFFFu, p, o, 8);
        if (seg == 0) out[b0 + row] = p + mb3[0];
    }
}

// ---------------------------------------------------------------------------
extern "C" void kernel_launch(void* const* d_in, const int* in_sizes, int n_in,
                              void* d_out, int out_size) {
    const int*   customer_id  = (const int*)d_in[0];
    const int*   cand_good    = (const int*)d_in[1];
    const int*   cand_class   = (const int*)d_in[2];
    const int*   hist_goods   = (const int*)d_in[3];
    const int*   hist_classes = (const int*)d_in[4];
    const float* user_table   = (const float*)d_in[5];
    const float* item_table   = (const float*)d_in[6];
    const float* cat_table    = (const float*)d_in[7];
    const float* aw1 = (const float*)d_in[8];
    const float* ab1 = (const float*)d_in[9];
    const float* aw2 = (const float*)d_in[10];
    const float* ab2 = (const float*)d_in[11];
    const float* mw1 = (const float*)d_in[12];
    const float* mb1 = (const float*)d_in[13];
    const float* mw2 = (const float*)d_in[14];
    const float* mb2 = (const float*)d_in[15];
    const float* mw3 = (const float*)d_in[16];
    const float* mb3 = (const float*)d_in[17];

    const int smemA = 16976 * 4;   // 67904 B -> 3 CTAs/SM
    const int smemB = 18176 * 4;   // 72704 B
    cudaFuncSetAttribute(din_attention_kernel,
                         cudaFuncAttributeMaxDynamicSharedMemorySize, smemA);
    cudaFuncSetAttribute(din_mlp_kernel,
                         cudaFuncAttributeMaxDynamicSharedMemorySize, smemB);

    din_prep<<<40, 256>>>(aw1, aw2, mw1, mw2);

    din_attention_kernel<<<NB / GA, 256, smemA>>>(
        customer_id, cand_good, cand_class, hist_goods, hist_classes,
        user_table, item_table, cat_table, ab1, ab2);

    din_mlp_kernel<<<NB / 32, 256, smemB>>>(
        mb1, mb2, mw3, mb3, (float*)d_out);
}

// round 17
// speedup vs baseline: 1.6334x; 1.6334x over previous
#include <cuda_runtime.h>
#include <math.h>

#define GA 16
#define NB 16384

__device__ float g_comb[NB * 160];
__device__ uint2 g_Pb[2560];      // attention W frags  [32 rows][80 n]
__device__ float g_AC[5120];      // A+C, [64 k][80 j]
__device__ float g_W2[80];
__device__ uint2 g_P1h[10240];    // mlp L1 W frags hi  [40 rows][256 n]
__device__ uint2 g_P1l[10240];    //                lo
__device__ uint2 g_P2h[8192];     // mlp L2 W frags hi  [64 rows][128 n]
__device__ uint2 g_P2l[8192];     //                lo

__device__ __forceinline__ unsigned pack_bf16x2(float lo, float hi) {
    unsigned r;   // low 16 bits <- lo, high 16 <- hi
    asm("cvt.rn.bf16x2.f32 %0, %1, %2;" : "=r"(r) : "f"(hi), "f"(lo));
    return r;
}
__device__ __forceinline__ float bflo(unsigned p) {
    return __uint_as_float(p << 16);
}
__device__ __forceinline__ float bfhi(unsigned p) {
    return __uint_as_float(p & 0xFFFF0000u);
}
__device__ __forceinline__ void mma_bf16(float* c,
                                         unsigned a0, unsigned a1, unsigned a2, unsigned a3,
                                         unsigned b0, unsigned b1) {
    asm volatile("mma.sync.aligned.m16n8k16.row.col.f32.bf16.bf16.f32 "
                 "{%0,%1,%2,%3}, {%4,%5,%6,%7}, {%8,%9}, {%0,%1,%2,%3};"
                 : "+f"(c[0]), "+f"(c[1]), "+f"(c[2]), "+f"(c[3])
                 : "r"(a0), "r"(a1), "r"(a2), "r"(a3), "r"(b0), "r"(b1));
}
__device__ __forceinline__ void cp_async16(float* smem_dst, const float* gsrc) {
    unsigned s = (unsigned)__cvta_generic_to_shared(smem_dst);
    asm volatile("cp.async.cg.shared.global [%0], [%1], 16;" :: "r"(s), "l"(gsrc));
}
__device__ __forceinline__ void cp_async_commit() {
    asm volatile("cp.async.commit_group;");
}
__device__ __forceinline__ void cp_async_wait_all() {
    asm volatile("cp.async.wait_group 0;" ::: "memory");
}
__device__ __forceinline__ void bar_grp(int id) {
    asm volatile("bar.sync %0, %1;" :: "r"(id), "r"(128) : "memory");
}

// ---------------------------------------------------------------------------
// Prep: attention W frags + AC + aw2, and MLP split-bf16 W frags.
// bf16 B-frag row r = ks*4+tig: pairs (k0,k0+1),(k0+8,k0+9), k0=ks*16+tig*2.
// ---------------------------------------------------------------------------
__global__ void din_prep(const float* __restrict__ aw1,
                         const float* __restrict__ aw2,
                         const float* __restrict__ mw1,
                         const float* __restrict__ mw2) {
    int idx = blockIdx.x * 256 + threadIdx.x;
    if (idx < 2560) {
        int r = idx / 80, n = idx - r * 80;
        int ks = r >> 2, tg = r & 3;
        int k0 = ks * 16 + tg * 2;
        float w[4];
        #pragma unroll
        for (int t = 0; t < 4; t++) {
            int kk = k0 + (t >> 1) * 8 + (t & 1);
            w[t] = (kk < 64)
                 ? aw1[(64 + kk) * 80 + n] - aw1[(128 + kk) * 80 + n]
                 : aw1[(192 + kk - 64) * 80 + n];
        }
        g_Pb[idx] = make_uint2(pack_bf16x2(w[0], w[1]), pack_bf16x2(w[2], w[3]));
    }
    if (idx < 5120) {
        int k = idx / 80, j = idx - k * 80;
        g_AC[idx] = aw1[k * 80 + j] + aw1[(128 + k) * 80 + j];
    }
    if (idx < 80) g_W2[idx] = aw2[idx];
    if (idx < 10240) {       // layer1 W frags, split hi/lo
        int r = idx >> 8, n = idx & 255;
        int k0 = (r >> 2) * 16 + (r & 3) * 2;
        float w0 = mw1[k0 * 256 + n],      w1 = mw1[(k0 + 1) * 256 + n];
        float w2 = mw1[(k0 + 8) * 256 + n], w3 = mw1[(k0 + 9) * 256 + n];
        unsigned h0 = pack_bf16x2(w0, w1), h1 = pack_bf16x2(w2, w3);
        unsigned l0 = pack_bf16x2(w0 - bflo(h0), w1 - bfhi(h0));
        unsigned l1 = pack_bf16x2(w2 - bflo(h1), w3 - bfhi(h1));
        g_P1h[idx] = make_uint2(h0, h1);
        g_P1l[idx] = make_uint2(l0, l1);
    }
    if (idx < 8192) {        // layer2 W frags, split hi/lo
        int r = idx >> 7, n = idx & 127;
        int k0 = (r >> 2) * 16 + (r & 3) * 2;
        float w0 = mw2[k0 * 128 + n],      w1 = mw2[(k0 + 1) * 128 + n];
        float w2 = mw2[(k0 + 8) * 128 + n], w3 = mw2[(k0 + 9) * 128 + n];
        unsigned h0 = pack_bf16x2(w0, w1), h1 = pack_bf16x2(w2, w3);
        unsigned l0 = pack_bf16x2(w0 - bflo(h0), w1 - bfhi(h0));
        unsigned l1 = pack_bf16x2(w2 - bflo(h1), w3 - bfhi(h1));
        g_P2h[idx] = make_uint2(h0, h1);
        g_P2l[idx] = make_uint2(l0, l1);
    }
}

// ---------------------------------------------------------------------------
// Attention: bf16 mma with smem B-frag staging (R15 structure), GA=16.
// smem 23504 floats = 94016 B, 2 CTAs/SM.
//  sPb 5376 | sH 4x3808 | sQ 1024 | sR 1280 | sW2 80 | sScore 128 | sWt 128
//  sPool 256
// ---------------------------------------------------------------------------
__global__ __launch_bounds__(256, 2)
void din_attention_kernel(
    const int* __restrict__ customer_id,
    const int* __restrict__ cand_good,
    const int* __restrict__ cand_class,
    const int* __restrict__ hist_goods,
    const int* __restrict__ hist_classes,
    const float* __restrict__ user_table,
    const float* __restrict__ item_table,
    const float* __restrict__ cat_table,
    const float* __restrict__ ab1,
    const float* __restrict__ ab2)
{
    extern __shared__ float sm[];
    uint2* sPb    = (uint2*)sm;        // 32 rows x 84 uint2 (5376 words)
    float* sH     = sm + 5376;         // 4 x 3808
    float* sQ     = sm + 20608;        // 1024
    float* sR     = sm + 21632;        // 1280 (stride 80)
    float* sW2    = sm + 22912;        // 80
    float* sScore = sm + 22992;        // 2 x 64
    float* sWt    = sm + 23120;        // 2 x 64
    float* sPool  = sm + 23248;        // 2 x 128

    const int tid  = threadIdx.x;
    const int warp = tid >> 5;
    const int lane = tid & 31;
    const int gid  = lane >> 2;
    const int tig  = lane & 3;
    const int grp  = warp >> 2;
    const int mt   = warp & 3;
    const int tg128 = tid & 127;
    const int b0   = blockIdx.x * GA;
    const float ab2v = __ldg(ab2);

    // ================= Phase A (CTA-wide, once) =========================
    for (int idx = tid; idx < GA * 64; idx += 256) {
        int g = idx >> 6, d = idx & 63;
        int b = b0 + g;
        float v = (d < 32) ? item_table[cand_good[b] * 32 + d]
                           : cat_table[cand_class[b] * 32 + (d - 32)];
        sQ[idx] = v;
        g_comb[b * 160 + 32 + d] = v;
    }
    for (int idx = tid; idx < GA * 32; idx += 256) {
        int g = idx >> 5, d = idx & 31;
        int b = b0 + g;
        g_comb[b * 160 + d] = user_table[customer_id[b] * 32 + d];
    }
    // stage AC into sH region (stride 80)
    float* sAC = sH;
    #pragma unroll
    for (int i = 0; i < 5; i++) {
        int f4 = tid + 256 * i;
        *(float4*)&sAC[f4 * 4] = __ldg((const float4*)g_AC + f4);
    }
    if (tid < 80) sW2[tid] = g_W2[tid];
    // stage packed bf16 B-frags: 1280 uint4 (40/row, smem stride 42 uint4)
    #pragma unroll
    for (int i = 0; i < 5; i++) {
        int v = tid + 256 * i;
        int row = v / 40, n2 = v - row * 40;
        ((uint4*)sm)[row * 42 + n2] = __ldg((const uint4*)g_Pb + v);
    }
    __syncthreads();
    // r[g][j] = ab1[j] + sum_k q[g][k]*AC[k][j]   (GA*80 = 1280 outputs)
    #pragma unroll
    for (int i = 0; i < 5; i++) {
        int idx = tid + 256 * i;
        int g = idx / 80, j = idx - g * 80;
        float v = __ldg(&ab1[j]);
        #pragma unroll 8
        for (int k = 0; k < 64; k++)
            v += sQ[g * 64 + k] * sAC[k * 80 + j];
        sR[idx] = v;
    }
    __syncthreads();   // sPb, sR ready; sAC region free for H buffers

    // ================= Phase B (two independent groups) =================
    const int barid = grp + 1;
    float* bufA = sH + (grp * 2) * 3808;
    float* bufB = sH + (grp * 2 + 1) * 3808;
    const int gfirst = grp * (GA / 2);

    {
        const int b = b0 + gfirst;
        for (int f4 = tg128; f4 < 800; f4 += 128) {
            int l = f4 >> 4, q4 = f4 & 15, d0 = q4 * 4;
            const float* src;
            if (d0 < 32) src = item_table + hist_goods[b * 50 + l] * 32 + d0;
            else         src = cat_table  + hist_classes[b * 50 + l] * 32 + (d0 - 32);
            cp_async16(&bufA[l * 68 + d0], src);
        }
        cp_async_commit();
        cp_async_wait_all();
        bar_grp(barid);
    }

    const int r_lo = mt * 16 + gid;
    const int r_hi = r_lo + 8;

    for (int i = 0; i < GA / 2; i++) {
        const int gg = gfirst + i;
        const int b  = b0 + gg;
        float* Hc = (i & 1) ? bufB : bufA;
        float* Ha = (i & 1) ? bufA : bufB;

        if (i < GA / 2 - 1) {
            const int bn = b + 1;
            for (int f4 = tg128; f4 < 800; f4 += 128) {
                int l = f4 >> 4, q4 = f4 & 15, d0 = q4 * 4;
                const float* src;
                if (d0 < 32) src = item_table + hist_goods[bn * 50 + l] * 32 + d0;
                else         src = cat_table  + hist_classes[bn * 50 + l] * 32 + (d0 - 32);
                cp_async16(&Ha[l * 68 + d0], src);
            }
            cp_async_commit();
        }
        int mk0 = 1, mk1 = 1;
        if (tig == 0) {
            if (r_lo < 50) mk0 = hist_goods[b * 50 + r_lo];
            if (r_hi < 50) mk1 = hist_goods[b * 50 + r_hi];
        }

        // ---- bf16 MMA: rows [mt*16, +16), all n=80, K=128 (8 chunks) ----
        float acc[10][4];
        #pragma unroll
        for (int nt = 0; nt < 10; nt++)
            acc[nt][0] = acc[nt][1] = acc[nt][2] = acc[nt][3] = 0.f;

        #pragma unroll
        for (int ks = 0; ks < 8; ks++) {
            unsigned a0, a1, a2, a3;
            if (ks < 4) {
                const int c = ks * 16 + tig * 2;
                float2 x0 = *(const float2*)&Hc[r_lo * 68 + c];
                float2 x1 = *(const float2*)&Hc[r_hi * 68 + c];
                float2 x2 = *(const float2*)&Hc[r_lo * 68 + c + 8];
                float2 x3 = *(const float2*)&Hc[r_hi * 68 + c + 8];
                a0 = pack_bf16x2(x0.x, x0.y);
                a1 = pack_bf16x2(x1.x, x1.y);
                a2 = pack_bf16x2(x2.x, x2.y);
                a3 = pack_bf16x2(x3.x, x3.y);
            } else {
                const int c = (ks - 4) * 16 + tig * 2;
                float2 x0 = *(const float2*)&Hc[r_lo * 68 + c];
                float2 x1 = *(const float2*)&Hc[r_hi * 68 + c];
                float2 x2 = *(const float2*)&Hc[r_lo * 68 + c + 8];
                float2 x3 = *(const float2*)&Hc[r_hi * 68 + c + 8];
                float2 ql = *(const float2*)&sQ[gg * 64 + c];
                float2 qh = *(const float2*)&sQ[gg * 64 + c + 8];
                a0 = pack_bf16x2(x0.x * ql.x, x0.y * ql.y);
                a1 = pack_bf16x2(x1.x * ql.x, x1.y * ql.y);
                a2 = pack_bf16x2(x2.x * qh.x, x2.y * qh.y);
                a3 = pack_bf16x2(x3.x * qh.x, x3.y * qh.y);
            }
            const uint2* P = sPb + (ks * 4 + tig) * 84;
            #pragma unroll
            for (int nt = 0; nt < 10; nt++) {
                uint2 bb = P[nt * 8 + gid];
                mma_bf16(acc[nt], a0, a1, a2, a3, bb.x, bb.y);
            }
        }

        // ---- epilogue: score = relu(S + r) . w2, reduce over tig ---------
        float slo = 0.f, shi = 0.f;
        #pragma unroll
        for (int nt = 0; nt < 10; nt++) {
            const int j0 = nt * 8 + tig * 2;
            float r0v = sR[gg * 80 + j0], r1v = sR[gg * 80 + j0 + 1];
            float w0 = sW2[j0], w1 = sW2[j0 + 1];
            slo += fmaxf(acc[nt][0] + r0v, 0.f) * w0
                 + fmaxf(acc[nt][1] + r1v, 0.f) * w1;
            shi += fmaxf(acc[nt][2] + r0v, 0.f) * w0
                 + fmaxf(acc[nt][3] + r1v, 0.f) * w1;
        }
        slo += __shfl_down_sync(0xFFFFFFFFu, slo, 2, 4);
        slo += __shfl_down_sync(0xFFFFFFFFu, slo, 1, 4);
        shi += __shfl_down_sync(0xFFFFFFFFu, shi, 2, 4);
        shi += __shfl_down_sync(0xFFFFFFFFu, shi, 1, 4);
        if (tig == 0) {
            if (r_lo < 50)
                sScore[grp * 64 + r_lo] = (mk0 == 0) ? -1e9f : slo + ab2v;
            if (r_hi < 50)
                sScore[grp * 64 + r_hi] = (mk1 == 0) ? -1e9f : shi + ab2v;
        }
        bar_grp(barid);   // bar1: scores ready

        if (mt == 0) {
            float s0 = (lane < 50) ? sScore[grp * 64 + lane] : -INFINITY;
            float s1 = (lane + 32 < 50) ? sScore[grp * 64 + lane + 32] : -INFINITY;
            float mx = fmaxf(s0, s1);
            #pragma unroll
            for (int o = 16; o > 0; o >>= 1)
                mx = fmaxf(mx, __shfl_xor_sync(0xFFFFFFFFu, mx, o));
            float e0 = (lane < 50) ? expf(s0 - mx) : 0.f;
            float e1 = (lane + 32 < 50) ? expf(s1 - mx) : 0.f;
            float sum = e0 + e1;
            #pragma unroll
            for (int o = 16; o > 0; o >>= 1)
                sum += __shfl_xor_sync(0xFFFFFFFFu, sum, o);
            float inv = 1.f / sum;
            if (lane < 50) sWt[grp * 64 + lane] = e0 * inv;
            if (lane + 32 < 50) sWt[grp * 64 + lane + 32] = e1 * inv;
        }
        bar_grp(barid);   // bar2: weights ready

        {
            int d = tg128 & 63, lh = tg128 >> 6;
            int l0 = lh * 25;
            float p = 0.f;
            #pragma unroll 5
            for (int l = l0; l < l0 + 25; l++)
                p += sWt[grp * 64 + l] * Hc[l * 68 + d];
            sPool[grp * 128 + tg128] = p;
        }
        if (i < GA / 2 - 1) cp_async_wait_all();
        bar_grp(barid);   // bar3: pool partials + next H ready
        if (tg128 < 64)
            g_comb[b * 160 + 96 + tg128] =
                sPool[grp * 128 + tg128] + sPool[grp * 128 + 64 + tg128];
    }
}

// ---------------------------------------------------------------------------
// MLP: split-bf16 tensor-core 160->256->128->1 (unchanged from R15-pass).
// ---------------------------------------------------------------------------
__global__ __launch_bounds__(256, 3)
void din_mlp_kernel(const float* __restrict__ mb1,
                    const float* __restrict__ mb2,
                    const float* __restrict__ mw3,
                    const float* __restrict__ mb3,
                    float* __restrict__ out)
{
    extern __shared__ float smf[];
    unsigned* sXh  = (unsigned*)smf;          // 32 x 84
    unsigned* sXl  = sXh + 2688;              // 32 x 84
    unsigned* sZ1h = sXl + 2688;              // 32 x 132
    unsigned* sZ1l = sZ1h + 4224;             // 32 x 132
    float*    sZ2  = (float*)(sZ1l + 4224);   // 32 x 132
    float*    sW3  = sZ2 + 4224;              // 128

    const int tid  = threadIdx.x;
    const int warp = tid >> 5;
    const int lane = tid & 31;
    const int gid  = lane >> 2;
    const int tig  = lane & 3;
    const int b0   = blockIdx.x * 32;

    #pragma unroll
    for (int i = 0; i < 10; i++) {
        int v = tid + 256 * i;
        int row = v / 80, w = v - row * 80;
        float2 x = *(const float2*)&g_comb[(b0 + row) * 160 + w * 2];
        unsigned h = pack_bf16x2(x.x, x.y);
        unsigned l = pack_bf16x2(x.x - bflo(h), x.y - bfhi(h));
        sXh[row * 84 + w] = h;
        sXl[row * 84 + w] = l;
    }
    if (tid < 128) sW3[tid] = mw3[tid];
    __syncthreads();

    const int nb1 = warp * 32;
    float acc1[4][2][4];
    #pragma unroll
    for (int nt = 0; nt < 4; nt++)
        #pragma unroll
        for (int m = 0; m < 2; m++)
            acc1[nt][m][0] = acc1[nt][m][1] = acc1[nt][m][2] = acc1[nt][m][3] = 0.f;

    #pragma unroll
    for (int ks = 0; ks < 10; ks++) {
        unsigned ah[2][4], al[2][4];
        #pragma unroll
        for (int m = 0; m < 2; m++) {
            int rl = (m * 16 + gid) * 84, rh = rl + 8 * 84;
            int wi = ks * 8 + tig;
            ah[m][0] = sXh[rl + wi];     al[m][0] = sXl[rl + wi];
            ah[m][1] = sXh[rh + wi];     al[m][1] = sXl[rh + wi];
            ah[m][2] = sXh[rl + wi + 4]; al[m][2] = sXl[rl + wi + 4];
            ah[m][3] = sXh[rh + wi + 4]; al[m][3] = sXl[rh + wi + 4];
        }
        #pragma unroll
        for (int nt = 0; nt < 4; nt++) {
            int bi = (ks * 4 + tig) * 256 + nb1 + nt * 8 + gid;
            uint2 bh = __ldg(&g_P1h[bi]);
            uint2 bl = __ldg(&g_P1l[bi]);
            #pragma unroll
            for (int m = 0; m < 2; m++) {
                mma_bf16(acc1[nt][m], ah[m][0], ah[m][1], ah[m][2], ah[m][3], bh.x, bh.y);
                mma_bf16(acc1[nt][m], al[m][0], al[m][1], al[m][2], al[m][3], bh.x, bh.y);
                mma_bf16(acc1[nt][m], ah[m][0], ah[m][1], ah[m][2], ah[m][3], bl.x, bl.y);
            }
        }
    }
    #pragma unroll
    for (int nt = 0; nt < 4; nt++) {
        int j0 = nb1 + nt * 8 + tig * 2;
        float b0v = __ldg(&mb1[j0]), b1v = __ldg(&mb1[j0 + 1]);
        int wx = (j0 >> 1);
        #pragma unroll
        for (int m = 0; m < 2; m++) {
            int rl = m * 16 + gid;
            float v0 = fmaxf(acc1[nt][m][0] + b0v, 0.f);
            float v1 = fmaxf(acc1[nt][m][1] + b1v, 0.f);
            float v2 = fmaxf(acc1[nt][m][2] + b0v, 0.f);
            float v3 = fmaxf(acc1[nt][m][3] + b1v, 0.f);
            unsigned h0 = pack_bf16x2(v0, v1);
            unsigned h1 = pack_bf16x2(v2, v3);
            sZ1h[rl * 132 + wx] = h0;
            sZ1l[rl * 132 + wx] = pack_bf16x2(v0 - bflo(h0), v1 - bfhi(h0));
            sZ1h[(rl + 8) * 132 + wx] = h1;
            sZ1l[(rl + 8) * 132 + wx] = pack_bf16x2(v2 - bflo(h1), v3 - bfhi(h1));
        }
    }
    __syncthreads();

    const int nb2 = warp * 16;
    float acc2[2][2][4];
    #pragma unroll
    for (int nt = 0; nt < 2; nt++)
        #pragma unroll
        for (int m = 0; m < 2; m++)
            acc2[nt][m][0] = acc2[nt][m][1] = acc2[nt][m][2] = acc2[nt][m][3] = 0.f;

    #pragma unroll
    for (int ks = 0; ks < 16; ks++) {
        unsigned ah[2][4], al[2][4];
        #pragma unroll
        for (int m = 0; m < 2; m++) {
            int rl = (m * 16 + gid) * 132, rh = rl + 8 * 132;
            int wi = ks * 8 + tig;
            ah[m][0] = sZ1h[rl + wi];     al[m][0] = sZ1l[rl + wi];
            ah[m][1] = sZ1h[rh + wi];     al[m][1] = sZ1l[rh + wi];
            ah[m][2] = sZ1h[rl + wi + 4]; al[m][2] = sZ1l[rl + wi + 4];
            ah[m][3] = sZ1h[rh + wi + 4]; al[m][3] = sZ1l[rh + wi + 4];
        }
        #pragma unroll
        for (int nt = 0; nt < 2; nt++) {
            int bi = (ks * 4 + tig) * 128 + nb2 + nt * 8 + gid;
            uint2 bh = __ldg(&g_P2h[bi]);
            uint2 bl = __ldg(&g_P2l[bi]);
            #pragma unroll
            for (int m = 0; m < 2; m++) {
                mma_bf16(acc2[nt][m], ah[m][0], ah[m][1], ah[m][2], ah[m][3], bh.x, bh.y);
                mma_bf16(acc2[nt][m], al[m][0], al[m][1], al[m][2], al[m][3], bh.x, bh.y);
                mma_bf16(acc2[nt][m], ah[m][0], ah[m][1], ah[m][2], ah[m][3], bl.x, bl.y);
            }
        }
    }
    #pragma unroll
    for (int nt = 0; nt < 2; nt++) {
        int j0 = nb2 + nt * 8 + tig * 2;
        float b0v = __ldg(&mb2[j0]), b1v = __ldg(&mb2[j0 + 1]);
        #pragma unroll
        for (int m = 0; m < 2; m++) {
            int rl = m * 16 + gid;
            float2 zlo = make_float2(fmaxf(acc2[nt][m][0] + b0v, 0.f),
                                     fmaxf(acc2[nt][m][1] + b1v, 0.f));
            float2 zhi = make_float2(fmaxf(acc2[nt][m][2] + b0v, 0.f),
                                     fmaxf(acc2[nt][m][3] + b1v, 0.f));
            *(float2*)&sZ2[rl * 132 + j0] = zlo;
            *(float2*)&sZ2[(rl + 8) * 132 + j0] = zhi;
        }
    }
    __syncthreads();

    {
        int row = tid >> 3, seg = tid & 7;
        float p = 0.f;
        #pragma unroll
        for (int k = seg * 16; k < seg * 16 + 16; k++)
            p += sZ2[row * 132 + k] * sW3[k];
        #pragma unroll
        for (int o = 4; o > 0; o >>= 1)
            p += __shfl_down_sync(0xFFFFFFFFu, p, o, 8);
        if (seg == 0) out[b0 + row] = p + mb3[0];
    }
}

// ---------------------------------------------------------------------------
extern "C" void kernel_launch(void* const* d_in, const int* in_sizes, int n_in,
                              void* d_out, int out_size) {
    const int*   customer_id  = (const int*)d_in[0];
    const int*   cand_good    = (const int*)d_in[1];
    const int*   cand_class   = (const int*)d_in[2];
    const int*   hist_goods   = (const int*)d_in[3];
    const int*   hist_classes = (const int*)d_in[4];
    const float* user_table   = (const float*)d_in[5];
    const float* item_table   = (const float*)d_in[6];
    const float* cat_table    = (const float*)d_in[7];
    const float* aw1 = (const float*)d_in[8];
    const float* ab1 = (const float*)d_in[9];
    const float* aw2 = (const float*)d_in[10];
    const float* ab2 = (const float*)d_in[11];
    const float* mw1 = (const float*)d_in[12];
    const float* mb1 = (const float*)d_in[13];
    const float* mw2 = (const float*)d_in[14];
    const float* mb2 = (const float*)d_in[15];
    const float* mw3 = (const float*)d_in[16];
    const float* mb3 = (const float*)d_in[17];

    const int smemA = 23504 * 4;   // 94016 B, 2 CTAs/SM
    const int smemB = 18176 * 4;   // 72704 B
    cudaFuncSetAttribute(din_attention_kernel,
                         cudaFuncAttributeMaxDynamicSharedMemorySize, smemA);
    cudaFuncSetAttribute(din_mlp_kernel,
                         cudaFuncAttributeMaxDynamicSharedMemorySize, smemB);

    din_prep<<<40, 256>>>(aw1, aw2, mw1, mw2);

    din_attention_kernel<<<NB / GA, 256, smemA>>>(
        customer_id, cand_good, cand_class, hist_goods, hist_classes,
        user_table, item_table, cat_table, ab1, ab2);

    din_mlp_kernel<<<NB / 32, 256, smemB>>>(
        mb1, mb2, mw3, mb3, (float*)d_out);
}